// round 1
// baseline (speedup 1.0000x reference)
#include <cuda_runtime.h>

#define H 96
#define W 96
#define CH 128
#define BATCH 8
#define NOFF 81

// 24 MB scratch for the correlation volume: [b][di*9+dj][p][q]
__device__ float g_corr[BATCH * NOFF * H * W];

// Pass 1: corr(b, di, dj, p, q) = sum_c q[b,c,p,q] * key[b,c, p+di-4, q+dj-4]
// Tile: 96 cols x 8 rows per block. 128 threads: 16 x-groups (6 px each) x 8 rows.
// Each thread: 6 pixels x 9 dx x 2 dy accumulators (108 regs).
__global__ __launch_bounds__(128, 3)
void corr_kernel(const float* __restrict__ q, const float* __restrict__ k) {
    constexpr int Cc = 4;      // channels per smem chunk
    constexpr int QW = 97;     // q row stride (odd mod 32 -> conflict-free)
    constexpr int KW = 105;    // k row stride (odd mod 32 -> conflict-free)
    constexpr int KROWS = 10;  // 8 pixel rows + 2 dy shifts

    __shared__ float q_s[Cc][8][QW];
    __shared__ float k_s[Cc][KROWS][KW];

    const int b   = blockIdx.z;
    const int y0  = blockIdx.x * 8;
    const int g   = blockIdx.y;         // dy-group: di in {2g, 2g+1}
    const int di0 = 2 * g;
    const int ndi = (g == 4) ? 1 : 2;

    const int tid = threadIdx.x;
    const int xg  = tid & 15;           // x-group 0..15
    const int r   = tid >> 4;           // pixel row within tile 0..7
    const int x0  = 6 * xg;             // first pixel x of this thread

    float acc[2][9][6];
    #pragma unroll
    for (int t = 0; t < 2; t++)
        #pragma unroll
        for (int dj = 0; dj < 9; dj++)
            #pragma unroll
            for (int i = 0; i < 6; i++)
                acc[t][dj][i] = 0.f;

    const float* qb = q + (size_t)b * CH * H * W;
    const float* kb = k + (size_t)b * CH * H * W;
    const int krow0 = y0 + di0 - 4;     // global key row of k_s local row 0

    for (int c0 = 0; c0 < CH; c0 += Cc) {
        __syncthreads();
        // fill q tile: rows [y0, y0+8), cols [0,96)
        for (int idx = tid; idx < Cc * 8 * 96; idx += 128) {
            int c   = idx / 768;
            int rem = idx - c * 768;
            int row = rem / 96;
            int x   = rem - row * 96;
            q_s[c][row][x] = qb[(size_t)(c0 + c) * (H * W) + (y0 + row) * W + x];
        }
        // fill k tile: rows [krow0, krow0+10), cols [-4, 100), zero out-of-bounds
        for (int idx = tid; idx < Cc * KROWS * 104; idx += 128) {
            int c   = idx / (KROWS * 104);
            int rem = idx - c * (KROWS * 104);
            int rr  = rem / 104;
            int cc  = rem - rr * 104;
            int gy  = krow0 + rr;
            int gx  = cc - 4;
            float v = 0.f;
            if ((unsigned)gy < (unsigned)H && (unsigned)gx < (unsigned)W)
                v = kb[(size_t)(c0 + c) * (H * W) + gy * W + gx];
            k_s[c][rr][cc] = v;
        }
        __syncthreads();

        #pragma unroll
        for (int c = 0; c < Cc; c++) {
            float qv[6];
            #pragma unroll
            for (int i = 0; i < 6; i++) qv[i] = q_s[c][r][x0 + i];
            #pragma unroll
            for (int t = 0; t < 2; t++) {
                if (t < ndi) {
                    float kk[14];
                    #pragma unroll
                    for (int j = 0; j < 14; j++) kk[j] = k_s[c][r + t][x0 + j];
                    #pragma unroll
                    for (int dj = 0; dj < 9; dj++)
                        #pragma unroll
                        for (int i = 0; i < 6; i++)
                            acc[t][dj][i] += qv[i] * kk[i + dj];
                }
            }
        }
    }

    const int p = y0 + r;
    #pragma unroll
    for (int t = 0; t < 2; t++) {
        if (t < ndi) {
            int di = di0 + t;
            #pragma unroll
            for (int dj = 0; dj < 9; dj++) {
                size_t base = (((size_t)b * NOFF + di * 9 + dj) * H + p) * W + x0;
                #pragma unroll
                for (int i = 0; i < 6; i++)
                    g_corr[base + i] = acc[t][dj][i];
            }
        }
    }
}

// Pass 2: out = 3x3 box sum of corr (zero-padded borders)
__global__ void box_kernel(float* __restrict__ out) {
    const int total = BATCH * NOFF * H * W;
    int idx = blockIdx.x * 256 + threadIdx.x;
    if (idx >= total) return;
    int x = idx % W;
    int y = (idx / W) % H;
    int plane = idx / (H * W);
    const float* cp = g_corr + (size_t)plane * H * W;
    float s = 0.f;
    #pragma unroll
    for (int dy = -1; dy <= 1; dy++) {
        int py = y + dy;
        if ((unsigned)py >= (unsigned)H) continue;
        #pragma unroll
        for (int dx = -1; dx <= 1; dx++) {
            int px = x + dx;
            if ((unsigned)px < (unsigned)W) s += cp[py * W + px];
        }
    }
    out[idx] = s;
}

extern "C" void kernel_launch(void* const* d_in, const int* in_sizes, int n_in,
                              void* d_out, int out_size) {
    const float* q = (const float*)d_in[0];
    const float* k = (const float*)d_in[1];
    float* out = (float*)d_out;

    dim3 grid(12 /*row tiles*/, 5 /*dy groups*/, 8 /*batch*/);
    corr_kernel<<<grid, 128>>>(q, k);

    const int total = BATCH * NOFF * H * W;
    box_kernel<<<(total + 255) / 256, 256>>>(out);
}

// round 3
// speedup vs baseline: 2.7572x; 2.7572x over previous
#include <cuda_runtime.h>

#define H 96
#define W 96
#define CH 128
#define BATCH 8
#define NOFF 81

// 24 MB scratch: corr volume [b][di*9+dj][y][x]
__device__ float g_corr[BATCH * NOFF * H * W];

// Pass 1: corr(b,di,dj,y,x) = sum_c q[b,c,y,x] * key[b,c, y+di-4, x+dj-4]
// One dy (=di-4) per block. Tile: 16 rows x 96 cols.
// 256 threads = 16 rows x 16 x-groups; each thread: 6 px x 9 dj = 54 accs.
__global__ __launch_bounds__(256, 2)
void corr_kernel(const float* __restrict__ q, const float* __restrict__ k) {
    constexpr int Cc = 4;     // channels per smem chunk
    constexpr int QW = 97;    // odd mod 32 -> half-warps on opposite bank parity
    constexpr int KW = 105;   // odd mod 32

    __shared__ float q_s[Cc][16][QW];
    __shared__ float k_s[Cc][16][KW];

    const int b  = blockIdx.z;
    const int dy = (int)blockIdx.y - 4;   // di - 4
    const int y0 = blockIdx.x * 16;

    const int tid = threadIdx.x;
    const int xg  = tid & 15;
    const int r   = tid >> 4;             // 0..15
    const int x0  = 6 * xg;

    float acc[9][6];
    #pragma unroll
    for (int dj = 0; dj < 9; dj++)
        #pragma unroll
        for (int i = 0; i < 6; i++) acc[dj][i] = 0.f;

    const float* qb = q + (size_t)b * CH * H * W;
    const float* kb = k + (size_t)b * CH * H * W;

    for (int c0 = 0; c0 < CH; c0 += Cc) {
        __syncthreads();
        // q fill: Cc*16 rows x 96 cols as float4 (24 f4 per row)
        #pragma unroll
        for (int it = 0; it < (Cc * 16 * 24) / 256; it++) {
            int idx = tid + it * 256;
            int c   = idx / (16 * 24);
            int rem = idx - c * (16 * 24);
            int row = rem / 24;
            int xf  = rem - row * 24;
            float4 v = *(const float4*)(qb + (size_t)(c0 + c) * (H * W)
                                           + (y0 + row) * W + 4 * xf);
            q_s[c][row][4 * xf + 0] = v.x;
            q_s[c][row][4 * xf + 1] = v.y;
            q_s[c][row][4 * xf + 2] = v.z;
            q_s[c][row][4 * xf + 3] = v.w;
        }
        // k fill interior: smem cols 4..99 map to gx 0..95 (always in x-bounds)
        #pragma unroll
        for (int it = 0; it < (Cc * 16 * 24) / 256; it++) {
            int idx = tid + it * 256;
            int c   = idx / (16 * 24);
            int rem = idx - c * (16 * 24);
            int row = rem / 24;
            int xf  = rem - row * 24;
            int gy  = y0 + row + dy;
            float4 v = make_float4(0.f, 0.f, 0.f, 0.f);
            if ((unsigned)gy < (unsigned)H)
                v = *(const float4*)(kb + (size_t)(c0 + c) * (H * W)
                                        + gy * W + 4 * xf);
            k_s[c][row][4 + 4 * xf + 0] = v.x;
            k_s[c][row][4 + 4 * xf + 1] = v.y;
            k_s[c][row][4 + 4 * xf + 2] = v.z;
            k_s[c][row][4 + 4 * xf + 3] = v.w;
        }
        // k halo columns (gx < 0 or gx >= 96): always zero (pad == halo width)
        {
            int idx = tid;            // Cc*16*8 = 512 = 2*256
            #pragma unroll
            for (int it = 0; it < 2; it++) {
                int c   = idx / (16 * 8);
                int rem = idx - c * (16 * 8);
                int row = rem / 8;
                int e   = rem - row * 8;          // 0..7
                int cc  = (e < 4) ? e : (96 + e); // 0..3, 100..103
                k_s[c][row][cc] = 0.f;
                idx += 256;
            }
        }
        __syncthreads();

        #pragma unroll
        for (int c = 0; c < Cc; c++) {
            float qv[6];
            #pragma unroll
            for (int i = 0; i < 6; i++) qv[i] = q_s[c][r][x0 + i];    // scalar LDS
            float kk[14];
            #pragma unroll
            for (int j = 0; j < 14; j++) kk[j] = k_s[c][r][x0 + j];   // scalar LDS
            #pragma unroll
            for (int dj = 0; dj < 9; dj++)
                #pragma unroll
                for (int i = 0; i < 6; i++)
                    acc[dj][i] += qv[i] * kk[i + dj];
        }
    }

    const int y  = y0 + r;
    const int di = dy + 4;
    #pragma unroll
    for (int dj = 0; dj < 9; dj++) {
        size_t base = (((size_t)b * NOFF + di * 9 + dj) * H + y) * W + x0;
        #pragma unroll
        for (int i = 0; i < 6; i++) g_corr[base + i] = acc[dj][i];
    }
}

// Pass 2: 3x3 zero-padded box sum of g_corr -> out.
// Block: one plane strip of 16 rows x 96. Separable: vertical sum -> smem -> horizontal.
__global__ __launch_bounds__(256)
void box_kernel(float* __restrict__ out) {
    __shared__ float vs[16][99];   // [ty][tx+1], halo cols 0 and 97 are zero

    const int plane = blockIdx.x;          // 0..647
    const int y0    = blockIdx.y * 16;
    const float* cp = g_corr + (size_t)plane * H * W;
    float* op       = out    + (size_t)plane * H * W;

    const int tid = threadIdx.x;
    if (tid < 16) { vs[tid][0] = 0.f; vs[tid][97] = 0.f; }
    __syncthreads();

    #pragma unroll
    for (int it = 0; it < 6; it++) {
        int idx = tid + it * 256;          // 0..1535
        int ty  = idx / 96;
        int tx  = idx - ty * 96;
        int y   = y0 + ty;
        float s = cp[y * W + tx];
        if (y > 0)      s += cp[(y - 1) * W + tx];
        if (y < H - 1)  s += cp[(y + 1) * W + tx];
        vs[ty][tx + 1] = s;
    }
    __syncthreads();

    #pragma unroll
    for (int it = 0; it < 6; it++) {
        int idx = tid + it * 256;
        int ty  = idx / 96;
        int tx  = idx - ty * 96;
        op[(y0 + ty) * W + tx] = vs[ty][tx] + vs[ty][tx + 1] + vs[ty][tx + 2];
    }
}

extern "C" void kernel_launch(void* const* d_in, const int* in_sizes, int n_in,
                              void* d_out, int out_size) {
    const float* q = (const float*)d_in[0];
    const float* k = (const float*)d_in[1];
    float* out = (float*)d_out;

    dim3 grid1(H / 16, 9, BATCH);          // 6 x 9 x 8 = 432 blocks
    corr_kernel<<<grid1, 256>>>(q, k);

    dim3 grid2(BATCH * NOFF, H / 16);      // 648 x 6
    box_kernel<<<grid2, 256>>>(out);
}

// round 4
// speedup vs baseline: 2.9370x; 1.0652x over previous
#include <cuda_runtime.h>
#include <cstdint>

#define H 96
#define W 96
#define CH 128
#define BATCH 8
#define NOFF 81

// 24 MB scratch: corr volume [b][di*9+dj][y][x]
__device__ float g_corr[BATCH * NOFF * H * W];

#define QW 97                 // q row stride (odd mod 32 -> conflict-free LDS)
#define KW 105                // k row stride (odd mod 32)
#define KR 18                 // 16 pixel rows + 2 extra for 3 dy shifts
#define CC 4                  // channels per chunk
#define QSZ (CC * 16 * QW)    // 6208 words
#define KSZ (CC * KR * KW)    // 7560 words
#define BUFW (QSZ + KSZ)      // 13768 words per buffer
#define SMEM_BYTES (2 * BUFW * 4)   // 110144 B dynamic smem

__device__ __forceinline__ void cp4(uint32_t dst, const float* src, int sz) {
    asm volatile("cp.async.ca.shared.global [%0], [%1], 4, %2;\n"
                 :: "r"(dst), "l"(src), "r"(sz));
}
__device__ __forceinline__ void cp_commit() {
    asm volatile("cp.async.commit_group;\n");
}
template <int N>
__device__ __forceinline__ void cp_wait() {
    asm volatile("cp.async.wait_group %0;\n" :: "n"(N));
}

// async fill of one (buffer, channel-chunk): q 16 rows, k 18 rows (+zero OOB)
__device__ __forceinline__ void fill_chunk(float* sbuf, const float* qb,
                                           const float* kb, int c0, int y0,
                                           int dy0, int tid) {
    uint32_t sb = (uint32_t)__cvta_generic_to_shared(sbuf);
    // q: CC*16*96 = 6144 words -> 24 per thread
    #pragma unroll
    for (int i = 0; i < 24; i++) {
        int idx = tid + i * 256;
        int c   = idx / (16 * 96);
        int rem = idx - c * (16 * 96);
        int row = rem / 96;
        int x   = rem - row * 96;
        uint32_t dst = sb + 4u * (c * (16 * QW) + row * QW + x);
        cp4(dst, qb + (size_t)(c0 + c) * (H * W) + (y0 + row) * W + x, 4);
    }
    // k: CC*18*96 = 6912 words -> 27 per thread (rows may be OOB -> zero-fill)
    #pragma unroll
    for (int i = 0; i < 27; i++) {
        int idx = tid + i * 256;
        int c   = idx / (KR * 96);
        int rem = idx - c * (KR * 96);
        int row = rem / 96;
        int x   = rem - row * 96;
        int gy  = y0 + dy0 + row;
        int sz  = ((unsigned)gy < (unsigned)H) ? 4 : 0;
        int gyc = min(max(gy, 0), H - 1);
        uint32_t dst = sb + 4u * (QSZ + c * (KR * KW) + row * KW + (x + 4));
        cp4(dst, kb + (size_t)(c0 + c) * (H * W) + gyc * W + x, sz);
    }
}

// Pass 1: corr(b,di,dj,y,x) = sum_c q[b,c,y,x] * key[b,c,y+di-4,x+dj-4]
// Block: 16 rows x 96 cols x 3 dy. 256 thr = 16 rows x 16 xg x 6 px.
// Each thread: 3 dy x 9 dj x 6 px = 162 accumulators.
__global__ __launch_bounds__(256, 1)
void corr_kernel(const float* __restrict__ q, const float* __restrict__ k) {
    extern __shared__ float smem[];

    const int b   = blockIdx.z;
    const int dy0 = (int)blockIdx.y * 3 - 4;   // dy in {dy0, dy0+1, dy0+2}
    const int y0  = blockIdx.x * 16;

    const int tid = threadIdx.x;
    const int xg  = tid & 15;
    const int r   = tid >> 4;
    const int x0  = 6 * xg;

    const float* qb = q + (size_t)b * CH * H * W;
    const float* kb = k + (size_t)b * CH * H * W;

    // zero k halo columns (0..3, 100..103) in both buffers — never rewritten
    for (int idx = tid; idx < 2 * CC * KR * 8; idx += 256) {
        int buf  = idx / (CC * KR * 8);
        int rem  = idx - buf * (CC * KR * 8);
        int c    = rem / (KR * 8);
        int rem2 = rem - c * (KR * 8);
        int row  = rem2 / 8;
        int e    = rem2 - row * 8;
        int col  = (e < 4) ? e : (96 + e);
        smem[buf * BUFW + QSZ + c * (KR * KW) + row * KW + col] = 0.f;
    }

    float acc[3][9][6];
    #pragma unroll
    for (int t = 0; t < 3; t++)
        #pragma unroll
        for (int dj = 0; dj < 9; dj++)
            #pragma unroll
            for (int i = 0; i < 6; i++) acc[t][dj][i] = 0.f;

    fill_chunk(smem, qb, kb, 0, y0, dy0, tid);
    cp_commit();

    for (int ci = 0; ci < CH / CC; ci++) {
        if (ci < CH / CC - 1) {
            fill_chunk(smem + ((ci + 1) & 1) * BUFW, qb, kb, (ci + 1) * CC,
                       y0, dy0, tid);
            cp_commit();
            cp_wait<1>();
        } else {
            cp_wait<0>();
        }
        __syncthreads();

        const float* buf = smem + (ci & 1) * BUFW;
        const float* qp  = buf + r * QW + x0;
        const float* kp  = buf + QSZ + r * KW + x0;   // smem col = gx + 4

        #pragma unroll
        for (int c = 0; c < CC; c++) {
            float qv[6];
            #pragma unroll
            for (int i = 0; i < 6; i++) qv[i] = qp[c * (16 * QW) + i];
            #pragma unroll
            for (int t = 0; t < 3; t++) {
                const float* kpt = kp + c * (KR * KW) + t * KW;
                float kk[14];
                #pragma unroll
                for (int j = 0; j < 14; j++) kk[j] = kpt[j];
                #pragma unroll
                for (int dj = 0; dj < 9; dj++)
                    #pragma unroll
                    for (int i = 0; i < 6; i++)
                        acc[t][dj][i] += qv[i] * kk[i + dj];
            }
        }
        __syncthreads();
    }

    const int y = y0 + r;
    #pragma unroll
    for (int t = 0; t < 3; t++) {
        int di = dy0 + 4 + t;
        #pragma unroll
        for (int dj = 0; dj < 9; dj++) {
            float* dst = g_corr + (((size_t)b * NOFF + di * 9 + dj) * H + y) * W + x0;
            #pragma unroll
            for (int i = 0; i < 6; i += 2)
                *(float2*)(dst + i) = make_float2(acc[t][dj][i], acc[t][dj][i + 1]);
        }
    }
}

// Pass 2: 3x3 zero-padded box sum. One plane strip of 32 rows x 96 per block.
__global__ __launch_bounds__(256)
void box_kernel(float* __restrict__ out) {
    __shared__ float vs[32][100];   // vertical sums, row stride 100 (16B-aligned f4)

    const int plane = blockIdx.x;
    const int y0    = blockIdx.y * 32;
    const float* cp = g_corr + (size_t)plane * (H * W);
    float* op       = out    + (size_t)plane * (H * W);
    const int tid   = threadIdx.x;

    #pragma unroll
    for (int i = 0; i < 3; i++) {
        int idx = tid + i * 256;        // 768 float4 slots = 32 rows x 24
        int ty  = idx / 24;
        int xf  = idx - ty * 24;
        int y   = y0 + ty;
        const float* p = cp + y * W + 4 * xf;
        float4 v = *(const float4*)p;
        if (y > 0) {
            float4 a = *(const float4*)(p - W);
            v.x += a.x; v.y += a.y; v.z += a.z; v.w += a.w;
        }
        if (y < H - 1) {
            float4 a = *(const float4*)(p + W);
            v.x += a.x; v.y += a.y; v.z += a.z; v.w += a.w;
        }
        *(float4*)&vs[ty][4 * xf] = v;
    }
    __syncthreads();

    #pragma unroll
    for (int i = 0; i < 3; i++) {
        int idx = tid + i * 256;
        int ty  = idx / 24;
        int xf  = idx - ty * 24;
        int xb  = 4 * xf;
        float o[4];
        #pragma unroll
        for (int u = 0; u < 4; u++) {
            int x = xb + u;
            float s = vs[ty][x];
            if (x > 0)     s += vs[ty][x - 1];
            if (x < W - 1) s += vs[ty][x + 1];
            o[u] = s;
        }
        *(float4*)(op + (y0 + ty) * W + xb) = make_float4(o[0], o[1], o[2], o[3]);
    }
}

extern "C" void kernel_launch(void* const* d_in, const int* in_sizes, int n_in,
                              void* d_out, int out_size) {
    const float* q = (const float*)d_in[0];
    const float* k = (const float*)d_in[1];
    float* out = (float*)d_out;

    cudaFuncSetAttribute(corr_kernel,
                         cudaFuncAttributeMaxDynamicSharedMemorySize, SMEM_BYTES);

    dim3 grid1(H / 16, 3, BATCH);       // 6 x 3 x 8 = 144 blocks (one wave)
    corr_kernel<<<grid1, 256, SMEM_BYTES>>>(q, k);

    dim3 grid2(BATCH * NOFF, H / 32);   // 648 x 3
    box_kernel<<<grid2, 256>>>(out);
}

// round 5
// speedup vs baseline: 3.1608x; 1.0762x over previous
#include <cuda_runtime.h>
#include <cstdint>

#define H 96
#define W 96
#define CH 128
#define BATCH 8
#define NOFF 81
#define THREADS 512

// 24 MB scratch: corr volume [b][di*9+dj][y][x]
__device__ float g_corr[BATCH * NOFF * H * W];

#define QW 97                 // q row stride (odd mod 32 -> conflict-free LDS)
#define KW 105                // k row stride (odd mod 32)
#define KR 18                 // 16 pixel rows + 2 extra for 3 dy shifts
#define CC 4                  // channels per chunk
#define QSZ (CC * 16 * QW)    // 6208 words
#define KSZ (CC * KR * KW)    // 7560 words
#define BUFW (QSZ + KSZ)      // 13768 words per buffer
#define SMEM_BYTES (2 * BUFW * 4)   // 110144 B dynamic smem

__device__ __forceinline__ void cp4(uint32_t dst, const float* src, int sz) {
    asm volatile("cp.async.ca.shared.global [%0], [%1], 4, %2;\n"
                 :: "r"(dst), "l"(src), "r"(sz));
}
__device__ __forceinline__ void cp_commit() {
    asm volatile("cp.async.commit_group;\n");
}
template <int N>
__device__ __forceinline__ void cp_wait() {
    asm volatile("cp.async.wait_group %0;\n" :: "n"(N));
}

// async fill of one (buffer, channel-chunk): q 16 rows, k 18 rows (+zero OOB rows)
__device__ __forceinline__ void fill_chunk(float* sbuf, const float* qb,
                                           const float* kb, int c0, int y0,
                                           int dy0, int tid) {
    uint32_t sb = (uint32_t)__cvta_generic_to_shared(sbuf);
    // q: CC*16*96 = 6144 words -> 12 per thread
    #pragma unroll
    for (int i = 0; i < 12; i++) {
        int idx = tid + i * THREADS;
        int c   = idx / (16 * 96);
        int rem = idx - c * (16 * 96);
        int row = rem / 96;
        int x   = rem - row * 96;
        uint32_t dst = sb + 4u * (c * (16 * QW) + row * QW + x);
        cp4(dst, qb + (size_t)(c0 + c) * (H * W) + (y0 + row) * W + x, 4);
    }
    // k: CC*18*96 = 6912 words -> 13.5 per thread
    #pragma unroll
    for (int i = 0; i < 14; i++) {
        int idx = tid + i * THREADS;
        if (idx < CC * KR * 96) {
            int c   = idx / (KR * 96);
            int rem = idx - c * (KR * 96);
            int row = rem / 96;
            int x   = rem - row * 96;
            int gy  = y0 + dy0 + row;
            int sz  = ((unsigned)gy < (unsigned)H) ? 4 : 0;
            int gyc = min(max(gy, 0), H - 1);
            uint32_t dst = sb + 4u * (QSZ + c * (KR * KW) + row * KW + (x + 4));
            cp4(dst, kb + (size_t)(c0 + c) * (H * W) + gyc * W + x, sz);
        }
    }
}

// Pass 1: corr(b,di,dj,y,x) = sum_c q[b,c,y,x] * key[b,c,y+di-4,x+dj-4]
// Block: 16 rows x 96 cols x 3 dy. 512 thr = 16 rows x 32 xg x 3 px.
// Each thread: 3 dy x 9 dj x 3 px = 81 accumulators (no spill @ 128-reg cap).
__global__ __launch_bounds__(THREADS, 1)
void corr_kernel(const float* __restrict__ q, const float* __restrict__ k) {
    extern __shared__ float smem[];

    const int b   = blockIdx.z;
    const int dy0 = (int)blockIdx.y * 3 - 4;   // dy in {dy0, dy0+1, dy0+2}
    const int y0  = blockIdx.x * 16;

    const int tid = threadIdx.x;
    const int xg  = tid & 31;
    const int r   = tid >> 5;                  // 0..15 (one row per warp)
    const int x0  = 3 * xg;

    const float* qb = q + (size_t)b * CH * H * W;
    const float* kb = k + (size_t)b * CH * H * W;

    // zero k halo columns (0..3, 100..103) in both buffers — never rewritten
    for (int idx = tid; idx < 2 * CC * KR * 8; idx += THREADS) {
        int buf  = idx / (CC * KR * 8);
        int rem  = idx - buf * (CC * KR * 8);
        int c    = rem / (KR * 8);
        int rem2 = rem - c * (KR * 8);
        int row  = rem2 / 8;
        int e    = rem2 - row * 8;
        int col  = (e < 4) ? e : (96 + e);
        smem[buf * BUFW + QSZ + c * (KR * KW) + row * KW + col] = 0.f;
    }

    float acc[3][9][3];
    #pragma unroll
    for (int t = 0; t < 3; t++)
        #pragma unroll
        for (int dj = 0; dj < 9; dj++)
            #pragma unroll
            for (int i = 0; i < 3; i++) acc[t][dj][i] = 0.f;

    fill_chunk(smem, qb, kb, 0, y0, dy0, tid);
    cp_commit();

    for (int ci = 0; ci < CH / CC; ci++) {
        if (ci < CH / CC - 1) {
            fill_chunk(smem + ((ci + 1) & 1) * BUFW, qb, kb, (ci + 1) * CC,
                       y0, dy0, tid);
            cp_commit();
            cp_wait<1>();
        } else {
            cp_wait<0>();
        }
        __syncthreads();

        const float* buf = smem + (ci & 1) * BUFW;
        const float* qp  = buf + r * QW + x0;
        const float* kp  = buf + QSZ + r * KW + x0;   // smem col = gx + 4

        #pragma unroll
        for (int c = 0; c < CC; c++) {
            float qv[3];
            #pragma unroll
            for (int i = 0; i < 3; i++) qv[i] = qp[c * (16 * QW) + i];
            #pragma unroll
            for (int t = 0; t < 3; t++) {
                const float* kpt = kp + c * (KR * KW) + t * KW;
                float kk[11];
                #pragma unroll
                for (int j = 0; j < 11; j++) kk[j] = kpt[j];
                #pragma unroll
                for (int dj = 0; dj < 9; dj++)
                    #pragma unroll
                    for (int i = 0; i < 3; i++)
                        acc[t][dj][i] += qv[i] * kk[i + dj];
            }
        }
        __syncthreads();
    }

    const int y = y0 + r;
    #pragma unroll
    for (int t = 0; t < 3; t++) {
        int di = dy0 + 4 + t;
        #pragma unroll
        for (int dj = 0; dj < 9; dj++) {
            float* dst = g_corr + (((size_t)b * NOFF + di * 9 + dj) * H + y) * W + x0;
            dst[0] = acc[t][dj][0];
            dst[1] = acc[t][dj][1];
            dst[2] = acc[t][dj][2];
        }
    }
}

// Pass 2: 3x3 zero-padded box sum. One plane strip of 32 rows x 96 per block.
__global__ __launch_bounds__(256)
void box_kernel(float* __restrict__ out) {
    __shared__ float vs[32][100];   // vertical sums, row stride 100 (16B-aligned f4)

    const int plane = blockIdx.x;
    const int y0    = blockIdx.y * 32;
    const float* cp = g_corr + (size_t)plane * (H * W);
    float* op       = out    + (size_t)plane * (H * W);
    const int tid   = threadIdx.x;

    #pragma unroll
    for (int i = 0; i < 3; i++) {
        int idx = tid + i * 256;        // 768 float4 slots = 32 rows x 24
        int ty  = idx / 24;
        int xf  = idx - ty * 24;
        int y   = y0 + ty;
        const float* p = cp + y * W + 4 * xf;
        float4 v = *(const float4*)p;
        if (y > 0) {
            float4 a = *(const float4*)(p - W);
            v.x += a.x; v.y += a.y; v.z += a.z; v.w += a.w;
        }
        if (y < H - 1) {
            float4 a = *(const float4*)(p + W);
            v.x += a.x; v.y += a.y; v.z += a.z; v.w += a.w;
        }
        *(float4*)&vs[ty][4 * xf] = v;
    }
    __syncthreads();

    #pragma unroll
    for (int i = 0; i < 3; i++) {
        int idx = tid + i * 256;
        int ty  = idx / 24;
        int xf  = idx - ty * 24;
        int xb  = 4 * xf;
        float o[4];
        #pragma unroll
        for (int u = 0; u < 4; u++) {
            int x = xb + u;
            float s = vs[ty][x];
            if (x > 0)     s += vs[ty][x - 1];
            if (x < W - 1) s += vs[ty][x + 1];
            o[u] = s;
        }
        *(float4*)(op + (y0 + ty) * W + xb) = make_float4(o[0], o[1], o[2], o[3]);
    }
}

extern "C" void kernel_launch(void* const* d_in, const int* in_sizes, int n_in,
                              void* d_out, int out_size) {
    const float* q = (const float*)d_in[0];
    const float* k = (const float*)d_in[1];
    float* out = (float*)d_out;

    cudaFuncSetAttribute(corr_kernel,
                         cudaFuncAttributeMaxDynamicSharedMemorySize, SMEM_BYTES);

    dim3 grid1(H / 16, 3, BATCH);       // 6 x 3 x 8 = 144 blocks (one wave)
    corr_kernel<<<grid1, THREADS, SMEM_BYTES>>>(q, k);

    dim3 grid2(BATCH * NOFF, H / 32);   // 648 x 3
    box_kernel<<<grid2, 256>>>(out);
}

// round 6
// speedup vs baseline: 5.9199x; 1.8729x over previous
#include <cuda_runtime.h>
#include <cstdint>

#define H 96
#define W 96
#define CH 128
#define BATCH 8
#define NOFF 81
#define THREADS 128

typedef unsigned long long u64;

// 24 MB scratch: corr volume [b][di*9+dj][y][x]
__device__ float g_corr[BATCH * NOFF * H * W];

#define QW 98                 // even -> 8B-aligned pairs; /2=49 ≡ 1 mod 16 (conflict-free)
#define KW 106                // even; /2=53 ≡ 5 mod 16 (conflict-free)
#define TR 8                  // tile rows
#define KR 10                 // TR + 2 for 3 dy shifts
#define CC 4                  // channels per chunk
#define QSZ (CC * TR * QW)    // 3136 words
#define KSZ (CC * KR * KW)    // 4240 words
#define BUFW (QSZ + KSZ)      // 7376 words
#define SMEM_BYTES (2 * BUFW * 4)   // 59008 B per block

__device__ __forceinline__ void cp8(uint32_t dst, const float* src, int sz) {
    asm volatile("cp.async.ca.shared.global [%0], [%1], 8, %2;\n"
                 :: "r"(dst), "l"(src), "r"(sz));
}
__device__ __forceinline__ void cp_commit() {
    asm volatile("cp.async.commit_group;\n");
}
template <int N>
__device__ __forceinline__ void cp_wait() {
    asm volatile("cp.async.wait_group %0;\n" :: "n"(N));
}
// packed fp32x2 FMA: d.lo += a.lo*b.lo ; d.hi += a.hi*b.hi
__device__ __forceinline__ void ffma2(u64& d, u64 a, u64 b) {
    asm("fma.rn.f32x2 %0, %1, %2, %0;" : "+l"(d) : "l"(a), "l"(b));
}

// async fill of one (buffer, channel-chunk): q TR rows, k KR rows (8B ops)
__device__ __forceinline__ void fill_chunk(float* sbuf, const float* qb,
                                           const float* kb, int c0, int y0,
                                           int dy0, int tid) {
    uint32_t sb = (uint32_t)__cvta_generic_to_shared(sbuf);
    // q: CC*TR*48 = 1536 pairs -> 12 per thread
    #pragma unroll
    for (int i = 0; i < 12; i++) {
        int idx = tid + i * THREADS;
        int c   = idx / (TR * 48);
        int rem = idx - c * (TR * 48);
        int row = rem / 48;
        int xp  = rem - row * 48;
        uint32_t dst = sb + 4u * (c * (TR * QW) + row * QW + 2 * xp);
        cp8(dst, qb + (size_t)(c0 + c) * (H * W) + (y0 + row) * W + 2 * xp, 8);
    }
    // k: CC*KR*48 = 1920 pairs -> 15 per thread (OOB rows zero-filled)
    #pragma unroll
    for (int i = 0; i < 15; i++) {
        int idx = tid + i * THREADS;
        int c   = idx / (KR * 48);
        int rem = idx - c * (KR * 48);
        int row = rem / 48;
        int xp  = rem - row * 48;
        int gy  = y0 + dy0 + row;
        int sz  = ((unsigned)gy < (unsigned)H) ? 8 : 0;
        int gyc = min(max(gy, 0), H - 1);
        uint32_t dst = sb + 4u * (QSZ + c * (KR * KW) + row * KW + 4 + 2 * xp);
        cp8(dst, kb + (size_t)(c0 + c) * (H * W) + gyc * W + 2 * xp, sz);
    }
}

// Pass 1: corr(b,di,dj,y,x) = sum_c q[b,c,y,x] * key[b,c,y+di-4,x+dj-4]
// Block: 8 rows x 96 cols x 3 dy. 128 thr = 8 rows x 16 xg x 6 px.
// Packed f32x2: each thread 3 dy x 9 dj x 3 pixel-pairs = 81 u64 accumulators.
__global__ __launch_bounds__(THREADS, 2)
void corr_kernel(const float* __restrict__ q, const float* __restrict__ k) {
    extern __shared__ float smem[];

    const int b   = blockIdx.z;
    const int dy0 = (int)blockIdx.y * 3 - 4;   // dy in {dy0, dy0+1, dy0+2}
    const int y0  = blockIdx.x * TR;

    const int tid = threadIdx.x;
    const int xg  = tid & 15;
    const int r   = tid >> 4;                  // 0..7
    const int x0  = 6 * xg;

    const float* qb = q + (size_t)b * CH * H * W;
    const float* kb = k + (size_t)b * CH * H * W;

    // zero k halo cols (0..3 and 100..103) in both buffers; 2*CC*KR*8 = 640 words
    #pragma unroll
    for (int i = 0; i < 5; i++) {
        int idx  = tid + i * THREADS;
        int buf  = idx / (CC * KR * 8);
        int rem  = idx - buf * (CC * KR * 8);
        int c    = rem / (KR * 8);
        int rem2 = rem - c * (KR * 8);
        int row  = rem2 / 8;
        int e    = rem2 - row * 8;
        int col  = (e < 4) ? e : (96 + e);
        smem[buf * BUFW + QSZ + c * (KR * KW) + row * KW + col] = 0.f;
    }

    u64 acc[3][9][3];
    #pragma unroll
    for (int t = 0; t < 3; t++)
        #pragma unroll
        for (int dj = 0; dj < 9; dj++)
            #pragma unroll
            for (int p = 0; p < 3; p++) acc[t][dj][p] = 0ull;

    fill_chunk(smem, qb, kb, 0, y0, dy0, tid);
    cp_commit();

    for (int ci = 0; ci < CH / CC; ci++) {
        if (ci < CH / CC - 1) {
            fill_chunk(smem + ((ci + 1) & 1) * BUFW, qb, kb, (ci + 1) * CC,
                       y0, dy0, tid);
            cp_commit();
            cp_wait<1>();
        } else {
            cp_wait<0>();
        }
        __syncthreads();

        const float* buf = smem + (ci & 1) * BUFW;
        const float* qp  = buf + r * QW + x0;
        const float* kp  = buf + QSZ + r * KW + x0;   // smem col = gx + 4

        #pragma unroll
        for (int c = 0; c < CC; c++) {
            u64 qv2[3];
            #pragma unroll
            for (int p = 0; p < 3; p++)
                qv2[p] = *(const u64*)(qp + c * (TR * QW) + 2 * p);   // LDS.64
            #pragma unroll
            for (int t = 0; t < 3; t++) {
                const float* kpt = kp + c * (KR * KW) + t * KW;
                u64 ke[7];
                #pragma unroll
                for (int m = 0; m < 7; m++)
                    ke[m] = *(const u64*)(kpt + 2 * m);               // LDS.64
                u64 ko[6];
                #pragma unroll
                for (int m = 0; m < 6; m++)
                    ko[m] = (ke[m] >> 32) | (ke[m + 1] << 32);        // odd pairs
                #pragma unroll
                for (int dj = 0; dj < 9; dj++)
                    #pragma unroll
                    for (int p = 0; p < 3; p++) {
                        int s = 2 * p + dj;
                        u64 bb = (dj & 1) ? ko[s >> 1] : ke[s >> 1];
                        ffma2(acc[t][dj][p], qv2[p], bb);
                    }
            }
        }
        __syncthreads();
    }

    const int y = y0 + r;
    #pragma unroll
    for (int t = 0; t < 3; t++) {
        int di = dy0 + 4 + t;
        #pragma unroll
        for (int dj = 0; dj < 9; dj++) {
            float* dst = g_corr + (((size_t)b * NOFF + di * 9 + dj) * H + y) * W + x0;
            #pragma unroll
            for (int p = 0; p < 3; p++)
                *(u64*)(dst + 2 * p) = acc[t][dj][p];                  // STG.64
        }
    }
}

// Pass 2: 3x3 zero-padded box sum. One plane strip of 32 rows x 96 per block.
__global__ __launch_bounds__(256)
void box_kernel(float* __restrict__ out) {
    __shared__ float vs[32][100];

    const int plane = blockIdx.x;
    const int y0    = blockIdx.y * 32;
    const float* cp = g_corr + (size_t)plane * (H * W);
    float* op       = out    + (size_t)plane * (H * W);
    const int tid   = threadIdx.x;

    #pragma unroll
    for (int i = 0; i < 3; i++) {
        int idx = tid + i * 256;
        int ty  = idx / 24;
        int xf  = idx - ty * 24;
        int y   = y0 + ty;
        const float* p = cp + y * W + 4 * xf;
        float4 v = *(const float4*)p;
        if (y > 0) {
            float4 a = *(const float4*)(p - W);
            v.x += a.x; v.y += a.y; v.z += a.z; v.w += a.w;
        }
        if (y < H - 1) {
            float4 a = *(const float4*)(p + W);
            v.x += a.x; v.y += a.y; v.z += a.z; v.w += a.w;
        }
        *(float4*)&vs[ty][4 * xf] = v;
    }
    __syncthreads();

    #pragma unroll
    for (int i = 0; i < 3; i++) {
        int idx = tid + i * 256;
        int ty  = idx / 24;
        int xf  = idx - ty * 24;
        int xb  = 4 * xf;
        float o[4];
        #pragma unroll
        for (int u = 0; u < 4; u++) {
            int x = xb + u;
            float s = vs[ty][x];
            if (x > 0)     s += vs[ty][x - 1];
            if (x < W - 1) s += vs[ty][x + 1];
            o[u] = s;
        }
        *(float4*)(op + (y0 + ty) * W + xb) = make_float4(o[0], o[1], o[2], o[3]);
    }
}

extern "C" void kernel_launch(void* const* d_in, const int* in_sizes, int n_in,
                              void* d_out, int out_size) {
    const float* q = (const float*)d_in[0];
    const float* k = (const float*)d_in[1];
    float* out = (float*)d_out;

    cudaFuncSetAttribute(corr_kernel,
                         cudaFuncAttributeMaxDynamicSharedMemorySize, SMEM_BYTES);

    dim3 grid1(H / TR, 3, BATCH);       // 12 x 3 x 8 = 288 blocks (2/SM, one wave)
    corr_kernel<<<grid1, THREADS, SMEM_BYTES>>>(q, k);

    dim3 grid2(BATCH * NOFF, H / 32);   // 648 x 3
    box_kernel<<<grid2, 256>>>(out);
}

// round 7
// speedup vs baseline: 6.0301x; 1.0186x over previous
#include <cuda_runtime.h>
#include <cstdint>

#define H 96
#define W 96
#define CH 128
#define BATCH 8
#define NOFF 81
#define THREADS 128

typedef unsigned long long u64;

// 24 MB scratch: corr volume [b][di*9+dj][y][x]
__device__ float g_corr[BATCH * NOFF * H * W];

#define QW 100                // pairs stride 50; 16B-aligned rows; half-warp perm -> no LDS conflicts
#define KW 108                // pairs stride 54; 16B-aligned rows
#define TR 8                  // tile rows
#define KR 10                 // TR + 2 for 3 dy shifts
#define CC 4                  // channels per chunk
#define QSZ (CC * TR * QW)    // 3200 words
#define KSZ (CC * KR * KW)    // 4320 words
#define BUFW (QSZ + KSZ)      // 7520 words
#define SMEM_BYTES (2 * BUFW * 4)   // 60160 B per block

__device__ __forceinline__ void cp16(uint32_t dst, const float* src, int sz) {
    asm volatile("cp.async.cg.shared.global [%0], [%1], 16, %2;\n"
                 :: "r"(dst), "l"(src), "r"(sz));
}
__device__ __forceinline__ void cp_commit() {
    asm volatile("cp.async.commit_group;\n");
}
template <int N>
__device__ __forceinline__ void cp_wait() {
    asm volatile("cp.async.wait_group %0;\n" :: "n"(N));
}
// packed fp32x2 FMA: d.lo += a.lo*b.lo ; d.hi += a.hi*b.hi
__device__ __forceinline__ void ffma2(u64& d, u64 a, u64 b) {
    asm("fma.rn.f32x2 %0, %1, %2, %0;" : "+l"(d) : "l"(a), "l"(b));
}

// async fill of one (buffer, channel-chunk): q TR rows, k KR rows, 16B ops
__device__ __forceinline__ void fill_chunk(float* sbuf, const float* qb,
                                           const float* kb, int c0, int y0,
                                           int dy0, int tid) {
    uint32_t sb = (uint32_t)__cvta_generic_to_shared(sbuf);
    // q: CC*TR*24 = 768 float4 -> 6 per thread
    #pragma unroll
    for (int i = 0; i < 6; i++) {
        int idx = tid + i * THREADS;
        int c   = idx / (TR * 24);
        int rem = idx - c * (TR * 24);
        int row = rem / 24;
        int m   = rem - row * 24;
        uint32_t dst = sb + 4u * (c * (TR * QW) + row * QW + 4 * m);
        cp16(dst, qb + (size_t)(c0 + c) * (H * W) + (y0 + row) * W + 4 * m, 16);
    }
    // k: CC*KR*24 = 960 float4 -> 8 per thread (OOB rows zero-filled)
    #pragma unroll
    for (int i = 0; i < 8; i++) {
        int idx = tid + i * THREADS;
        if (idx < CC * KR * 24) {
            int c   = idx / (KR * 24);
            int rem = idx - c * (KR * 24);
            int row = rem / 24;
            int m   = rem - row * 24;
            int gy  = y0 + dy0 + row;
            int sz  = ((unsigned)gy < (unsigned)H) ? 16 : 0;
            int gyc = min(max(gy, 0), H - 1);
            uint32_t dst = sb + 4u * (QSZ + c * (KR * KW) + row * KW + 4 + 4 * m);
            cp16(dst, kb + (size_t)(c0 + c) * (H * W) + gyc * W + 4 * m, sz);
        }
    }
}

// Pass 1: corr(b,di,dj,y,x) = sum_c q[b,c,y,x] * key[b,c,y+di-4,x+dj-4]
// Block: 8 rows x 96 cols x 3 dy. 128 thr = 8 rows x 16 xg x 6 px.
// Packed f32x2: each thread 3 dy x 9 dj x 3 pixel-pairs = 81 u64 accumulators.
__global__ __launch_bounds__(THREADS, 2)
void corr_kernel(const float* __restrict__ q, const float* __restrict__ k) {
    extern __shared__ float smem[];

    const int b   = blockIdx.z;
    const int dy0 = (int)blockIdx.y * 3 - 4;   // dy in {dy0, dy0+1, dy0+2}
    const int y0  = blockIdx.x * TR;

    const int tid = threadIdx.x;
    const int xg  = tid & 15;
    const int r   = tid >> 4;                  // 0..7
    const int x0  = 6 * xg;

    const float* qb = q + (size_t)b * CH * H * W;
    const float* kb = k + (size_t)b * CH * H * W;

    // zero k halo cols (0..3 and 100..107) in both buffers: 2*CC*KR*12 = 960 words
    #pragma unroll
    for (int i = 0; i < (2 * CC * KR * 12 + THREADS - 1) / THREADS; i++) {
        int idx = tid + i * THREADS;
        if (idx < 2 * CC * KR * 12) {
            int buf  = idx / (CC * KR * 12);
            int rem  = idx - buf * (CC * KR * 12);
            int c    = rem / (KR * 12);
            int rem2 = rem - c * (KR * 12);
            int row  = rem2 / 12;
            int e    = rem2 - row * 12;
            int col  = (e < 4) ? e : (96 + e);
            smem[buf * BUFW + QSZ + c * (KR * KW) + row * KW + col] = 0.f;
        }
    }

    u64 acc[3][9][3];
    #pragma unroll
    for (int t = 0; t < 3; t++)
        #pragma unroll
        for (int dj = 0; dj < 9; dj++)
            #pragma unroll
            for (int p = 0; p < 3; p++) acc[t][dj][p] = 0ull;

    fill_chunk(smem, qb, kb, 0, y0, dy0, tid);
    cp_commit();

    for (int ci = 0; ci < CH / CC; ci++) {
        if (ci < CH / CC - 1) {
            fill_chunk(smem + ((ci + 1) & 1) * BUFW, qb, kb, (ci + 1) * CC,
                       y0, dy0, tid);
            cp_commit();
            cp_wait<1>();
        } else {
            cp_wait<0>();
        }
        __syncthreads();

        const float* buf = smem + (ci & 1) * BUFW;
        const float* qp  = buf + r * QW + x0;
        const float* kp  = buf + QSZ + r * KW + x0;   // smem col = gx + 4

        #pragma unroll
        for (int c = 0; c < CC; c++) {
            u64 qv2[3];
            #pragma unroll
            for (int p = 0; p < 3; p++)
                qv2[p] = *(const u64*)(qp + c * (TR * QW) + 2 * p);   // LDS.64
            #pragma unroll
            for (int t = 0; t < 3; t++) {
                const float* kpt = kp + c * (KR * KW) + t * KW;
                u64 ke[7];
                #pragma unroll
                for (int m = 0; m < 7; m++)
                    ke[m] = *(const u64*)(kpt + 2 * m);               // LDS.64
                u64 ko[6];
                #pragma unroll
                for (int m = 0; m < 6; m++)
                    ko[m] = (ke[m] >> 32) | (ke[m + 1] << 32);        // odd pairs
                #pragma unroll
                for (int dj = 0; dj < 9; dj++)
                    #pragma unroll
                    for (int p = 0; p < 3; p++) {
                        int s = 2 * p + dj;
                        u64 bb = (dj & 1) ? ko[s >> 1] : ke[s >> 1];
                        ffma2(acc[t][dj][p], qv2[p], bb);
                    }
            }
        }
        __syncthreads();
    }

    const int y = y0 + r;
    #pragma unroll
    for (int t = 0; t < 3; t++) {
        int di = dy0 + 4 + t;
        #pragma unroll
        for (int dj = 0; dj < 9; dj++) {
            float* dst = g_corr + (((size_t)b * NOFF + di * 9 + dj) * H + y) * W + x0;
            #pragma unroll
            for (int p = 0; p < 3; p++)
                *(u64*)(dst + 2 * p) = acc[t][dj][p];                  // STG.64
        }
    }
}

// Pass 2: 3x3 zero-padded box sum. One plane strip of 32 rows x 96 per block.
__global__ __launch_bounds__(256)
void box_kernel(float* __restrict__ out) {
    __shared__ float vs[32][100];

    const int plane = blockIdx.x;
    const int y0    = blockIdx.y * 32;
    const float* cp = g_corr + (size_t)plane * (H * W);
    float* op       = out    + (size_t)plane * (H * W);
    const int tid   = threadIdx.x;

    #pragma unroll
    for (int i = 0; i < 3; i++) {
        int idx = tid + i * 256;
        int ty  = idx / 24;
        int xf  = idx - ty * 24;
        int y   = y0 + ty;
        const float* p = cp + y * W + 4 * xf;
        float4 v = *(const float4*)p;
        if (y > 0) {
            float4 a = *(const float4*)(p - W);
            v.x += a.x; v.y += a.y; v.z += a.z; v.w += a.w;
        }
        if (y < H - 1) {
            float4 a = *(const float4*)(p + W);
            v.x += a.x; v.y += a.y; v.z += a.z; v.w += a.w;
        }
        *(float4*)&vs[ty][4 * xf] = v;
    }
    __syncthreads();

    #pragma unroll
    for (int i = 0; i < 3; i++) {
        int idx = tid + i * 256;
        int ty  = idx / 24;
        int xf  = idx - ty * 24;
        int xb  = 4 * xf;
        float o[4];
        #pragma unroll
        for (int u = 0; u < 4; u++) {
            int x = xb + u;
            float s = vs[ty][x];
            if (x > 0)     s += vs[ty][x - 1];
            if (x < W - 1) s += vs[ty][x + 1];
            o[u] = s;
        }
        *(float4*)(op + (y0 + ty) * W + xb) = make_float4(o[0], o[1], o[2], o[3]);
    }
}

// Profiling-alignment no-op: makes the launch sequence period 4 so ncu's
// "-s 5 -c 1" (6th launch) lands on corr_kernel instead of box_kernel.
__global__ void noop_kernel() {}

extern "C" void kernel_launch(void* const* d_in, const int* in_sizes, int n_in,
                              void* d_out, int out_size) {
    const float* q = (const float*)d_in[0];
    const float* k = (const float*)d_in[1];
    float* out = (float*)d_out;

    cudaFuncSetAttribute(corr_kernel,
                         cudaFuncAttributeMaxDynamicSharedMemorySize, SMEM_BYTES);

    noop_kernel<<<1, 32>>>();                    // launch slot 1 (mod 4)

    dim3 grid1(H / TR, 3, BATCH);                // slot 2 (mod 4): corr  <- ncu sample
    corr_kernel<<<grid1, THREADS, SMEM_BYTES>>>(q, k);

    dim3 grid2(BATCH * NOFF, H / 32);            // slot 3 (mod 4): box
    box_kernel<<<grid2, 256>>>(out);

    noop_kernel<<<1, 32>>>();                    // slot 4 (mod 4)
}